// round 3
// baseline (speedup 1.0000x reference)
#include <cuda_runtime.h>
#include <cstdint>

// spspmm via counting-sort by target row:
//   1) histogram counts of acd[0]
//   2) exclusive scan -> segment offsets
//   3) scatter pair-ids into perm, bucketed by target
//   4) one 8-thread group per output row: accumulate segment in registers,
//      single coalesced float4 store (no atomics, no zero-fill, no RMW read)

#define TAR_CAP 2100000
#define M_CAP   4200000
#define SCAN_T  1024
#define SCAN_I  4
#define SCAN_CHUNK (SCAN_T * SCAN_I)   // 4096

__device__ int g_count[TAR_CAP];
__device__ int g_offset[TAR_CAP];
__device__ int g_cursor[TAR_CAP];
__device__ int g_perm[M_CAP];
__device__ int g_blocksums[1024];

__global__ void zero_counts_kernel(int n) {
    int i = blockIdx.x * blockDim.x + threadIdx.x;
    int stride = gridDim.x * blockDim.x;
    for (; i < n; i += stride) g_count[i] = 0;
}

__global__ void hist_kernel(const int* __restrict__ acd, int M) {
    int i = blockIdx.x * blockDim.x + threadIdx.x;
    if (i < M) atomicAdd(&g_count[acd[i]], 1);
}

// Pass 1: per-block exclusive scan of counts; block totals to g_blocksums.
__global__ void scan1_kernel(int N) {
    __shared__ int sh[SCAN_T];
    int b = blockIdx.x;
    int t = threadIdx.x;
    int base = b * SCAN_CHUNK + t * SCAN_I;
    int v[SCAN_I];
    int s = 0;
#pragma unroll
    for (int k = 0; k < SCAN_I; k++) {
        int idx = base + k;
        v[k] = (idx < N) ? g_count[idx] : 0;
        s += v[k];
    }
    sh[t] = s;
    __syncthreads();
    for (int off = 1; off < SCAN_T; off <<= 1) {
        int x = (t >= off) ? sh[t - off] : 0;
        __syncthreads();
        sh[t] += x;
        __syncthreads();
    }
    int excl = sh[t] - s;
    if (t == SCAN_T - 1) g_blocksums[b] = sh[SCAN_T - 1];
    int run = excl;
#pragma unroll
    for (int k = 0; k < SCAN_I; k++) {
        int idx = base + k;
        if (idx < N) g_offset[idx] = run;
        run += v[k];
    }
}

// Pass 2: single-block exclusive scan of block sums (nb <= 1024).
__global__ void scan2_kernel(int nb) {
    __shared__ int sh[SCAN_T];
    int t = threadIdx.x;
    int orig = (t < nb) ? g_blocksums[t] : 0;
    sh[t] = orig;
    __syncthreads();
    for (int off = 1; off < SCAN_T; off <<= 1) {
        int x = (t >= off) ? sh[t - off] : 0;
        __syncthreads();
        sh[t] += x;
        __syncthreads();
    }
    if (t < nb) g_blocksums[t] = sh[t] - orig;
}

// Pass 3: add block prefix; initialize cursor.
__global__ void scan3_kernel(int N) {
    int i = blockIdx.x * blockDim.x + threadIdx.x;
    int stride = gridDim.x * blockDim.x;
    for (; i < N; i += stride) {
        int o = g_offset[i] + g_blocksums[i / SCAN_CHUNK];
        g_offset[i] = o;
        g_cursor[i] = o;
    }
}

__global__ void scatter_kernel(const int* __restrict__ acd, int M) {
    int i = blockIdx.x * blockDim.x + threadIdx.x;
    if (i < M) {
        int a = acd[i];
        int pos = atomicAdd(&g_cursor[a], 1);
        g_perm[pos] = i;
    }
}

// One 8-thread group per output row.
__global__ void __launch_bounds__(256) gather_kernel(
    const float4* __restrict__ A,
    const float4* __restrict__ B,
    const int* __restrict__ acd,   // [3, M]
    float* __restrict__ out,
    int M, int tar)
{
    long long gid = (long long)blockIdx.x * blockDim.x + threadIdx.x;
    int r = (int)(gid >> 3);
    int lane = (int)(gid & 7);
    if (r >= tar) return;

    int off = __ldg(&g_offset[r]);
    int cnt = __ldg(&g_count[r]);

    float4 acc = make_float4(0.f, 0.f, 0.f, 0.f);
    for (int j = 0; j < cnt; j++) {
        int i = __ldg(&g_perm[off + j]);
        long long c = (long long)__ldg(&acd[M + i]);
        long long d = (long long)__ldg(&acd[2 * M + i]);
        float4 av = __ldg(&A[c * 8 + lane]);
        float4 bv = __ldg(&B[d * 8 + lane]);
        acc.x += av.x * bv.x;
        acc.y += av.y * bv.y;
        acc.z += av.z * bv.z;
        acc.w += av.w * bv.w;
    }
    ((float4*)(out + (long long)r * 32))[lane] = acc;
}

extern "C" void kernel_launch(void* const* d_in, const int* in_sizes, int n_in,
                              void* d_out, int out_size) {
    const float4* A = (const float4*)d_in[0];
    const float4* B = (const float4*)d_in[1];
    const int* acd = (const int*)d_in[2];
    float* out = (float*)d_out;

    int M = in_sizes[2] / 3;
    int tar = out_size / 32;
    if (tar > TAR_CAP || M > M_CAP) return;  // capacity guard (never hit)

    int nb_scan = (tar + SCAN_CHUNK - 1) / SCAN_CHUNK;

    zero_counts_kernel<<<1184, 256>>>(tar);
    hist_kernel<<<(M + 255) / 256, 256>>>(acd, M);
    scan1_kernel<<<nb_scan, SCAN_T>>>(tar);
    scan2_kernel<<<1, SCAN_T>>>(nb_scan);
    scan3_kernel<<<1184, 256>>>(tar);
    scatter_kernel<<<(M + 255) / 256, 256>>>(acd, M);

    long long total_threads = (long long)tar * 8;
    long long blocks = (total_threads + 255) / 256;
    gather_kernel<<<(unsigned)blocks, 256>>>(A, B, acd, out, M, tar);
}

// round 4
// speedup vs baseline: 1.2170x; 1.2170x over previous
#include <cuda_runtime.h>
#include <cstdint>

// spspmm via counting-sort by target row, with (c,d) materialized at scatter
// time so the hot gather kernel does only sequential index reads:
//   1) histogram counts of acd[0]
//   2) exclusive scan -> segment offsets (+cursor init)
//   3) scatter (c,d) int2 into per-target buckets (32MB, L2-resident)
//   4) one 8-thread group per output row: accumulate segment in registers,
//      single coalesced float4 store (no atomics, no zero-fill, no RMW)

#define TAR_CAP 2100000
#define M_CAP   4200000
#define SCAN_T  1024
#define SCAN_I  4
#define SCAN_CHUNK (SCAN_T * SCAN_I)   // 4096

__device__ int  g_count[TAR_CAP];
__device__ int  g_offset[TAR_CAP];
__device__ int  g_cursor[TAR_CAP];
__device__ int2 g_cd[M_CAP];
__device__ int  g_blocksums[1024];

__global__ void zero_counts_kernel(int n) {
    int i = blockIdx.x * blockDim.x + threadIdx.x;
    int stride = gridDim.x * blockDim.x;
    for (; i < n; i += stride) g_count[i] = 0;
}

__global__ void hist_kernel(const int* __restrict__ acd, int M) {
    int i = blockIdx.x * blockDim.x + threadIdx.x;
    if (i < M) atomicAdd(&g_count[acd[i]], 1);
}

// Pass 1: per-block exclusive scan of counts; block totals to g_blocksums.
__global__ void scan1_kernel(int N) {
    __shared__ int sh[SCAN_T];
    int b = blockIdx.x;
    int t = threadIdx.x;
    int base = b * SCAN_CHUNK + t * SCAN_I;
    int v[SCAN_I];
    int s = 0;
#pragma unroll
    for (int k = 0; k < SCAN_I; k++) {
        int idx = base + k;
        v[k] = (idx < N) ? g_count[idx] : 0;
        s += v[k];
    }
    sh[t] = s;
    __syncthreads();
    for (int off = 1; off < SCAN_T; off <<= 1) {
        int x = (t >= off) ? sh[t - off] : 0;
        __syncthreads();
        sh[t] += x;
        __syncthreads();
    }
    int excl = sh[t] - s;
    if (t == SCAN_T - 1) g_blocksums[b] = sh[SCAN_T - 1];
    int run = excl;
#pragma unroll
    for (int k = 0; k < SCAN_I; k++) {
        int idx = base + k;
        if (idx < N) g_offset[idx] = run;
        run += v[k];
    }
}

// Pass 2: single-block exclusive scan of block sums (nb <= 1024).
__global__ void scan2_kernel(int nb) {
    __shared__ int sh[SCAN_T];
    int t = threadIdx.x;
    int orig = (t < nb) ? g_blocksums[t] : 0;
    sh[t] = orig;
    __syncthreads();
    for (int off = 1; off < SCAN_T; off <<= 1) {
        int x = (t >= off) ? sh[t - off] : 0;
        __syncthreads();
        sh[t] += x;
        __syncthreads();
    }
    if (t < nb) g_blocksums[t] = sh[t] - orig;
}

// Pass 3: add block prefix; initialize cursor.
__global__ void scan3_kernel(int N) {
    int i = blockIdx.x * blockDim.x + threadIdx.x;
    int stride = gridDim.x * blockDim.x;
    for (; i < N; i += stride) {
        int o = g_offset[i] + g_blocksums[i / SCAN_CHUNK];
        g_offset[i] = o;
        g_cursor[i] = o;
    }
}

// Scatter (c,d) directly — hot kernel never touches acd again.
__global__ void scatter_kernel(const int* __restrict__ acd, int M) {
    int i = blockIdx.x * blockDim.x + threadIdx.x;
    if (i < M) {
        int a = acd[i];
        int c = acd[M + i];
        int d = acd[2 * M + i];
        int pos = atomicAdd(&g_cursor[a], 1);
        g_cd[pos] = make_int2(c, d);
    }
}

// One 8-thread group per output row; sequential (c,d) reads, register accum,
// single coalesced store.
__global__ void __launch_bounds__(256) gather_kernel(
    const float4* __restrict__ A,
    const float4* __restrict__ B,
    float* __restrict__ out,
    int tar)
{
    long long gid = (long long)blockIdx.x * blockDim.x + threadIdx.x;
    int r = (int)(gid >> 3);
    int lane = (int)(gid & 7);
    if (r >= tar) return;

    int off = __ldg(&g_offset[r]);
    int cnt = __ldg(&g_count[r]);

    float4 acc = make_float4(0.f, 0.f, 0.f, 0.f);
    for (int j = 0; j < cnt; j++) {
        int2 cd = __ldg(&g_cd[off + j]);
        float4 av = __ldg(&A[(long long)cd.x * 8 + lane]);
        float4 bv = __ldg(&B[(long long)cd.y * 8 + lane]);
        acc.x += av.x * bv.x;
        acc.y += av.y * bv.y;
        acc.z += av.z * bv.z;
        acc.w += av.w * bv.w;
    }
    ((float4*)(out + (long long)r * 32))[lane] = acc;
}

extern "C" void kernel_launch(void* const* d_in, const int* in_sizes, int n_in,
                              void* d_out, int out_size) {
    const float4* A = (const float4*)d_in[0];
    const float4* B = (const float4*)d_in[1];
    const int* acd = (const int*)d_in[2];
    float* out = (float*)d_out;

    int M = in_sizes[2] / 3;
    int tar = out_size / 32;
    if (tar > TAR_CAP || M > M_CAP) return;  // capacity guard (never hit)

    int nb_scan = (tar + SCAN_CHUNK - 1) / SCAN_CHUNK;

    zero_counts_kernel<<<1184, 256>>>(tar);
    hist_kernel<<<(M + 255) / 256, 256>>>(acd, M);
    scan1_kernel<<<nb_scan, SCAN_T>>>(tar);
    scan2_kernel<<<1, SCAN_T>>>(nb_scan);
    scan3_kernel<<<1184, 256>>>(tar);
    scatter_kernel<<<(M + 255) / 256, 256>>>(acd, M);

    long long total_threads = (long long)tar * 8;
    long long blocks = (total_threads + 255) / 256;
    gather_kernel<<<(unsigned)blocks, 256>>>(A, B, out, tar);
}